// round 14
// baseline (speedup 1.0000x reference)
#include <cuda_runtime.h>
#include <math.h>

// Problem shape (fixed by dataset): B=8, T=4096, F=1024
#define B_DIM 8
#define T_DIM 4096
#define F_DIM 1024
#define F4 (F_DIM / 4)            // 256 float4 per row
#define ROWS_PER_BLK 32
#define NBLK_PER_B (T_DIM / ROWS_PER_BLK)       // 128
#define RED_TILES (B_DIM * NBLK_PER_B)          // 1024
#define OUT_ROWS 8
#define OUT_PER_B (T_DIM / OUT_ROWS)            // 512
#define OUT_TILES (B_DIM * OUT_PER_B)           // 4096
#define GRID_BLOCKS 592                         // 4/SM x 148 SMs (co-resident)

// Scratch (no device-memory allocations). Zero at load; every launch restores
// state to zero so graph replays are deterministic.
__device__ float g_ksum[B_DIM * F_DIM];
__device__ float g_kc[B_DIM * F_DIM];
__device__ float g_invkd[B_DIM];
__device__ int   g_len[B_DIM];
__device__ int   g_done[B_DIM];
__device__ int   g_ready[B_DIM];
__device__ int   g_cdone[B_DIM];

// ---------------------------------------------------------------------------
__device__ __forceinline__ float block_reduce1(float v) {
    __shared__ float sh[8];
    #pragma unroll
    for (int o = 16; o; o >>= 1) v += __shfl_xor_sync(0xffffffffu, v, o);
    int w = threadIdx.x >> 5, l = threadIdx.x & 31;
    if (l == 0) sh[w] = v;
    __syncthreads();
    if (w == 0) {
        v = (l < 8) ? sh[l] : 0.f;
        #pragma unroll
        for (int o = 4; o; o >>= 1) v += __shfl_xor_sync(0xffffffffu, v, o);
        if (l == 0) sh[0] = v;
    }
    __syncthreads();
    float r = sh[0];
    __syncthreads();
    return r;
}

// ---------------------------------------------------------------------------
// Persistent kernel: each of the 592 co-resident blocks strides phase-1
// reduce tiles (batch-ascending), then flows into phase-2 output tiles,
// gating on per-batch readiness flags. No launch boundary, no parked
// spinners (a block only waits after finishing its phase-1 share, by which
// time early batches are complete).
__global__ void __launch_bounds__(256, 4) pfsa_persistent(
        const float4* __restrict__ x,
        const int* __restrict__ mask,
        float4* __restrict__ out) {
    const int tid = threadIdx.x;
    const int warp = tid >> 5;
    const int lane = tid & 31;

    __shared__ int scount;
    __shared__ int slast;

    // =================== PHASE 1: masked channel reduce ===================
    for (int tile = blockIdx.x; tile < RED_TILES; tile += GRID_BLOCKS) {
        const int b = tile >> 7;                    // tile / NBLK_PER_B
        const int t0 = (tile & 127) * ROWS_PER_BLK;

        if (tid < 32) {
            int mv = mask[b * T_DIM + t0 + tid];
            unsigned bal = __ballot_sync(0xffffffffu, mv != 0);
            if (tid == 0) scount = __popc(bal);
        }
        __syncthreads();
        const int count = scount;

        const size_t rowbase = ((size_t)b * T_DIM + t0) * F4;

        if (count > 0) {
            const float4* xb = x + rowbase + tid;
            float ax = 0.f, ay = 0.f, az = 0.f, aw = 0.f;
            #pragma unroll 8
            for (int r = 0; r < count; ++r) {
                float4 v = __ldcg(&xb[(size_t)r * F4]);
                ax += v.x; ay += v.y; az += v.z; aw += v.w;
            }
            float* dst = &g_ksum[b * F_DIM + tid * 4];
            atomicAdd(dst + 0, ax);
            atomicAdd(dst + 1, ay);
            atomicAdd(dst + 2, az);
            atomicAdd(dst + 3, aw);
            if (tid == 0) atomicAdd(&g_len[b], count);
        }

        // ---- completion ticket ----
        __threadfence();
        __syncthreads();
        if (tid == 0)
            slast = (atomicAdd(&g_done[b], 1) == NBLK_PER_B - 1) ? 1 : 0;
        __syncthreads();

        if (slast) {
            // last tile of this batch: per-batch stats, then raise ready flag
            const float L = (float)g_len[b];
            const float invL = 1.0f / L;

            float kv[4];
            float s = 0.f;
            #pragma unroll
            for (int j = 0; j < 4; ++j) {
                kv[j] = g_ksum[b * F_DIM + tid * 4 + j] * invL;
                s += kv[j];
            }
            float meank = block_reduce1(s) * (1.0f / (float)F_DIM);

            float ss = 0.f;
            #pragma unroll
            for (int j = 0; j < 4; ++j) {
                float kc = kv[j] - meank;
                g_kc[b * F_DIM + tid * 4 + j] = kc;
                ss += kc * kc;
                g_ksum[b * F_DIM + tid * 4 + j] = 0.0f;  // restore for replay
            }
            float kd2 = block_reduce1(ss);
            if (tid == 0) {
                g_invkd[b] = rsqrtf(kd2);
                g_len[b] = 0;
                g_done[b] = 0;
                __threadfence();             // publish stats before flag
                atomicExch(&g_ready[b], 1);
            }
        }
    }

    // =================== PHASE 2: warp-per-row output ======================
    for (int tile = blockIdx.x; tile < OUT_TILES; tile += GRID_BLOCKS) {
        const int b = tile >> 9;                    // tile / OUT_PER_B
        const int t0 = (tile & 511) * OUT_ROWS;
        const int t = t0 + warp;
        const size_t base = ((size_t)b * T_DIM + t) * F4;

        const bool anyValid = (mask[b * T_DIM + t0] != 0);  // monotone prefix

        if (anyValid) {
            if (tid == 0) {
                while (atomicAdd(&g_ready[b], 0) == 0) __nanosleep(64);
            }
            __syncthreads();
            __threadfence();   // order kc/invkd reads after the flag
        }

        if (!mask[b * T_DIM + t]) {
            const float4 z = make_float4(0.f, 0.f, 0.f, 0.f);
            #pragma unroll
            for (int j = 0; j < 8; ++j)
                __stcs(&out[base + lane + j * 32], z);
        } else {
            float4 v[8];
            #pragma unroll
            for (int j = 0; j < 8; ++j) v[j] = __ldcs(&x[base + lane + j * 32]);

            float s1 = 0.f, s2 = 0.f;
            #pragma unroll
            for (int j = 0; j < 8; ++j) {
                s1 += v[j].x + v[j].y + v[j].z + v[j].w;
                s2 += v[j].x * v[j].x + v[j].y * v[j].y + v[j].z * v[j].z + v[j].w * v[j].w;
            }

            const float4* kcb = (const float4*)&g_kc[b * F_DIM];
            float s3 = 0.f;
            #pragma unroll
            for (int h = 0; h < 2; ++h) {
                float4 kc[4];
                #pragma unroll
                for (int j = 0; j < 4; ++j) kc[j] = kcb[lane + (h * 4 + j) * 32];
                #pragma unroll
                for (int j = 0; j < 4; ++j) {
                    const float4& w = v[h * 4 + j];
                    s3 += w.x * kc[j].x + w.y * kc[j].y + w.z * kc[j].z + w.w * kc[j].w;
                }
            }

            #pragma unroll
            for (int o = 16; o; o >>= 1) {
                s1 += __shfl_xor_sync(0xffffffffu, s1, o);
                s2 += __shfl_xor_sync(0xffffffffu, s2, o);
                s3 += __shfl_xor_sync(0xffffffffu, s3, o);
            }

            float qd2 = s2 - s1 * s1 * (1.0f / (float)F_DIM);
            float C = s3 * rsqrtf(qd2) * g_invkd[b];
            float A = 1.0f / (1.0f + __expf(C));   // (1 - sigmoid(C))^ALPHA

            #pragma unroll
            for (int j = 0; j < 8; ++j) {
                v[j].x *= A; v[j].y *= A; v[j].z *= A; v[j].w *= A;
                __stcs(&out[base + lane + j * 32], v[j]);
            }
        }

        // ---- reset ticket: last out-tile of batch b restores flags ----
        __syncthreads();
        if (tid == 0) {
            if (atomicAdd(&g_cdone[b], 1) == OUT_PER_B - 1) {
                g_cdone[b] = 0;
                atomicExch(&g_ready[b], 0);
            }
        }
    }
}

// ---------------------------------------------------------------------------
extern "C" void kernel_launch(void* const* d_in, const int* in_sizes, int n_in,
                              void* d_out, int out_size) {
    const float4* x = (const float4*)d_in[0];
    const int* mask = (const int*)d_in[1];
    float4* out = (float4*)d_out;

    pfsa_persistent<<<GRID_BLOCKS, 256>>>(x, mask, out);
}